// round 4
// baseline (speedup 1.0000x reference)
#include <cuda_runtime.h>

// ReadGate, 3-kernel pipeline:
//  k0: q[b] = emb[query[b]] @ qW.T + qb                  (tiny)
//  k1: grid (B, SPLIT): stream memory[b, s-th chunk], no-max online softmax,
//      write unnormalized partial pooled + partial expsum to scratch
//  k2: combine partials, normalize, out = pooled @ oW.T + ob  (tiny)
// Main kernel is a pure streamer: no smem staging, no barriers before mainloop.

constexpr int Bn = 2048;
constexpr int Mn = 2048;
constexpr int Dn = 64;
constexpr int Vn = 64;
constexpr int THREADS = 256;
constexpr int NHW = 16;                       // half-warps per CTA
constexpr int UNROLL = 4;                     // m-rows per half-warp per iter
constexpr int SPLIT = 4;                      // M-chunks per batch row
constexpr int MCHUNK = Mn / SPLIT;            // 512
constexpr int ITERS = MCHUNK / (NHW * UNROLL);// 8

__device__ float g_q[Bn * Dn];                // projected queries
__device__ float g_pooled[Bn * SPLIT * Dn];   // unnormalized partial pooled
__device__ float g_sum[Bn * SPLIT];           // partial exp-sums

// ---------------- k0: query projection ----------------
__global__ __launch_bounds__(Dn)
void qproj_kernel(const int* __restrict__ query,
                  const float* __restrict__ emb,
                  const float* __restrict__ qW,
                  const float* __restrict__ qb)
{
    __shared__ float e_sh[Dn];
    const int b = blockIdx.x, tid = threadIdx.x;
    e_sh[tid] = emb[query[b] * Dn + tid];
    __syncthreads();
    float acc = qb[tid];
    #pragma unroll
    for (int k = 0; k < Dn; ++k)
        acc = fmaf(e_sh[k], __ldg(qW + tid * Dn + k), acc);
    g_q[b * Dn + tid] = acc;
}

// ---------------- k1: main streamer ----------------
__device__ __forceinline__
void load_tile(float4 v[UNROLL], const float4* __restrict__ mrow, int it, int hw)
{
    #pragma unroll
    for (int j = 0; j < UNROLL; ++j)
        v[j] = __ldcs(mrow + (size_t)(hw + it * (NHW * UNROLL) + j * NHW) * (Dn / 4));
}

__device__ __forceinline__
void consume_tile(const float4 v[UNROLL],
                  float q0, float q1, float q2, float q3,
                  float& rsum, float& a0, float& a1, float& a2, float& a3)
{
    #pragma unroll
    for (int j = 0; j < UNROLL; ++j) {
        float s = fmaf(v[j].x, q0, fmaf(v[j].y, q1, fmaf(v[j].z, q2, v[j].w * q3)));
        s += __shfl_xor_sync(0xffffffffu, s, 8);
        s += __shfl_xor_sync(0xffffffffu, s, 4);
        s += __shfl_xor_sync(0xffffffffu, s, 2);
        s += __shfl_xor_sync(0xffffffffu, s, 1);
        const float p = __expf(s * 0.125f);   // no max-subtraction: |s/8| <~ 5
        rsum += p;
        a0 = fmaf(p, v[j].x, a0);
        a1 = fmaf(p, v[j].y, a1);
        a2 = fmaf(p, v[j].z, a2);
        a3 = fmaf(p, v[j].w, a3);
    }
}

__global__ __launch_bounds__(THREADS, 4)
void stream_kernel(const float* __restrict__ memory)
{
    __shared__ float pooled_sh[NHW][Dn];
    __shared__ float sum_sh[NHW];

    const int b   = blockIdx.x;
    const int s   = blockIdx.y;
    const int tid = threadIdx.x;
    const int hw   = tid >> 4;
    const int lane = tid & 15;

    // per-thread q slice (L2/L1-hot broadcast)
    const float4 qv = *reinterpret_cast<const float4*>(g_q + b * Dn + lane * 4);
    const float q0 = qv.x, q1 = qv.y, q2 = qv.z, q3 = qv.w;

    const float4* __restrict__ mrow =
        reinterpret_cast<const float4*>(memory + (size_t)b * (Mn * Dn)
                                               + (size_t)s * (MCHUNK * Dn)) + lane;

    float rsum = 0.f;
    float a0 = 0.f, a1 = 0.f, a2 = 0.f, a3 = 0.f;

    float4 va[UNROLL], vb[UNROLL];
    load_tile(va, mrow, 0, hw);

    #pragma unroll 1
    for (int it = 0; it < ITERS - 2; it += 2) {
        load_tile(vb, mrow, it + 1, hw);
        consume_tile(va, q0, q1, q2, q3, rsum, a0, a1, a2, a3);
        load_tile(va, mrow, it + 2, hw);
        consume_tile(vb, q0, q1, q2, q3, rsum, a0, a1, a2, a3);
    }
    load_tile(vb, mrow, ITERS - 1, hw);
    consume_tile(va, q0, q1, q2, q3, rsum, a0, a1, a2, a3);
    consume_tile(vb, q0, q1, q2, q3, rsum, a0, a1, a2, a3);

    pooled_sh[hw][lane * 4 + 0] = a0;
    pooled_sh[hw][lane * 4 + 1] = a1;
    pooled_sh[hw][lane * 4 + 2] = a2;
    pooled_sh[hw][lane * 4 + 3] = a3;
    if (lane == 0) sum_sh[hw] = rsum;
    __syncthreads();

    if (tid < Dn) {
        float pl = 0.f;
        #pragma unroll
        for (int p = 0; p < NHW; ++p) pl += pooled_sh[p][tid];
        g_pooled[((size_t)b * SPLIT + s) * Dn + tid] = pl;
        if (tid == 0) {
            float gs = 0.f;
            #pragma unroll
            for (int p = 0; p < NHW; ++p) gs += sum_sh[p];
            g_sum[b * SPLIT + s] = gs;
        }
    }
}

// ---------------- k2: combine + output projection ----------------
__global__ __launch_bounds__(Vn)
void combine_kernel(const float* __restrict__ oW,
                    const float* __restrict__ ob,
                    float* __restrict__ out)
{
    __shared__ float p_sh[Dn];
    const int b = blockIdx.x, tid = threadIdx.x;

    float pl = 0.f;
    #pragma unroll
    for (int s = 0; s < SPLIT; ++s)
        pl += g_pooled[((size_t)b * SPLIT + s) * Dn + tid];
    float gs = 0.f;
    #pragma unroll
    for (int s = 0; s < SPLIT; ++s)
        gs += g_sum[b * SPLIT + s];
    p_sh[tid] = pl / gs;
    __syncthreads();

    float acc = ob[tid];
    #pragma unroll
    for (int d = 0; d < Dn; ++d)
        acc = fmaf(p_sh[d], __ldg(oW + tid * Dn + d), acc);
    out[(size_t)b * Vn + tid] = acc;
}

extern "C" void kernel_launch(void* const* d_in, const int* in_sizes, int n_in,
                              void* d_out, int out_size)
{
    const int*   query  = (const int*)  d_in[0];
    const float* memory = (const float*)d_in[1];
    const float* emb    = (const float*)d_in[2];
    const float* qW     = (const float*)d_in[3];
    const float* qb     = (const float*)d_in[4];
    const float* oW     = (const float*)d_in[5];
    const float* ob     = (const float*)d_in[6];
    float* out = (float*)d_out;

    qproj_kernel<<<Bn, Dn>>>(query, emb, qW, qb);
    stream_kernel<<<dim3(Bn, SPLIT), THREADS>>>(memory);
    combine_kernel<<<Bn, Vn>>>(oW, ob, out);
}

// round 5
// speedup vs baseline: 1.3129x; 1.3129x over previous
#include <cuda_runtime.h>

// ReadGate: q = emb[query]@qW.T + qb ; sims = <q, memory[b,m]>/8 ; w = softmax(sims)
// pooled = sum_m w*memory[b,m] ; out = pooled@oW.T + ob
// Single-pass streaming, no-max softmax (|sims/8| <~ 5, exp exact-safe in fp32).
// Prefetch-next-tile pipeline; prefetch index CLAMPED (last iter re-prefetches the
// L2-resident current tile instead of cold tile 0 -> no wasted DRAM traffic).

constexpr int Bn = 2048;
constexpr int Mn = 2048;
constexpr int Dn = 64;
constexpr int Vn = 64;
constexpr int THREADS = 256;
constexpr int NHW = 16;      // half-warps per CTA
constexpr int UNROLL = 4;    // m-rows per half-warp per outer iter
constexpr int ITERS = Mn / (NHW * UNROLL);   // 32

__global__ __launch_bounds__(THREADS, 4)
void readgate_kernel(const int* __restrict__ query,
                     const float* __restrict__ memory,
                     const float* __restrict__ emb,
                     const float* __restrict__ qW,
                     const float* __restrict__ qb,
                     const float* __restrict__ oW,
                     const float* __restrict__ ob,
                     float* __restrict__ out)
{
    __shared__ float w_sh[Dn * 65];          // staged qW, then reused for oW (pad 65)
    __shared__ float e_sh[Dn];
    __shared__ float q_sh[Dn];               // q vector, then normalized pooled
    __shared__ float pooled_sh[NHW][Dn];
    __shared__ float sum_sh[NHW];

    const int b   = blockIdx.x;
    const int tid = threadIdx.x;

    // ---- stage qW (padded, conflict-free) + emb row ----
    #pragma unroll
    for (int i = tid; i < Dn * Dn; i += THREADS)
        w_sh[(i >> 6) * 65 + (i & 63)] = qW[i];
    if (tid < Dn)
        e_sh[tid] = emb[query[b] * Dn + tid];
    __syncthreads();

    // ---- q[d] = qb[d] + sum_k e[k]*qW[d,k] ----
    if (tid < Dn) {
        float acc = qb[tid];
        #pragma unroll
        for (int k = 0; k < Dn; ++k)
            acc = fmaf(e_sh[k], w_sh[tid * 65 + k], acc);
        q_sh[tid] = acc;
    }
    __syncthreads();

    // ---- stage oW now; post-mainloop barrier orders it before use ----
    #pragma unroll
    for (int i = tid; i < Dn * Dn; i += THREADS)
        w_sh[(i >> 6) * 65 + (i & 63)] = oW[i];

    // ---- main streaming loop ----
    const int hw   = tid >> 4;   // 0..15
    const int lane = tid & 15;   // 0..15
    const float q0 = q_sh[lane * 4 + 0];
    const float q1 = q_sh[lane * 4 + 1];
    const float q2 = q_sh[lane * 4 + 2];
    const float q3 = q_sh[lane * 4 + 3];

    const float4* __restrict__ mrow =
        reinterpret_cast<const float4*>(memory + (size_t)b * (Mn * Dn)) + lane;

    float rsum = 0.f;
    float a0 = 0.f, a1 = 0.f, a2 = 0.f, a3 = 0.f;

    // prologue: load iter 0
    float4 v[UNROLL];
    #pragma unroll
    for (int j = 0; j < UNROLL; ++j)
        v[j] = __ldcs(mrow + (size_t)(hw + j * NHW) * (Dn / 4));

    #pragma unroll 1
    for (int it = 0; it < ITERS; ++it) {
        // prefetch next iteration, clamped: last iter re-fetches current (L2-hot) tile
        const int nit = (it + 1 < ITERS) ? (it + 1) : (ITERS - 1);
        float4 nv[UNROLL];
        #pragma unroll
        for (int j = 0; j < UNROLL; ++j)
            nv[j] = __ldcs(mrow + (size_t)(hw + nit * (NHW * UNROLL) + j * NHW) * (Dn / 4));

        #pragma unroll
        for (int j = 0; j < UNROLL; ++j) {
            float s = fmaf(v[j].x, q0, fmaf(v[j].y, q1, fmaf(v[j].z, q2, v[j].w * q3)));
            s += __shfl_xor_sync(0xffffffffu, s, 8);
            s += __shfl_xor_sync(0xffffffffu, s, 4);
            s += __shfl_xor_sync(0xffffffffu, s, 2);
            s += __shfl_xor_sync(0xffffffffu, s, 1);
            const float p = __expf(s * 0.125f);   // no max-subtraction needed
            rsum += p;
            a0 = fmaf(p, v[j].x, a0);
            a1 = fmaf(p, v[j].y, a1);
            a2 = fmaf(p, v[j].z, a2);
            a3 = fmaf(p, v[j].w, a3);
        }

        #pragma unroll
        for (int j = 0; j < UNROLL; ++j) v[j] = nv[j];
    }

    pooled_sh[hw][lane * 4 + 0] = a0;
    pooled_sh[hw][lane * 4 + 1] = a1;
    pooled_sh[hw][lane * 4 + 2] = a2;
    pooled_sh[hw][lane * 4 + 3] = a3;
    if (lane == 0) sum_sh[hw] = rsum;
    __syncthreads();

    // ---- combine partials; normalize pooled ----
    if (tid < Dn) {
        float gsum = 0.f, pl = 0.f;
        #pragma unroll
        for (int p = 0; p < NHW; ++p) {
            gsum += sum_sh[p];
            pl   += pooled_sh[p][tid];
        }
        q_sh[tid] = pl / gsum;
    }
    __syncthreads();

    // ---- out[b,v] = ob[v] + sum_d pooled[d]*oW[v,d] ----
    if (tid < Vn) {
        float acc = ob[tid];
        #pragma unroll
        for (int d = 0; d < Dn; ++d)
            acc = fmaf(q_sh[d], w_sh[tid * 65 + d], acc);
        out[(size_t)b * Vn + tid] = acc;
    }
}

extern "C" void kernel_launch(void* const* d_in, const int* in_sizes, int n_in,
                              void* d_out, int out_size)
{
    const int*   query  = (const int*)  d_in[0];
    const float* memory = (const float*)d_in[1];
    const float* emb    = (const float*)d_in[2];
    const float* qW     = (const float*)d_in[3];
    const float* qb     = (const float*)d_in[4];
    const float* oW     = (const float*)d_in[5];
    const float* ob     = (const float*)d_in[6];
    float* out = (float*)d_out;

    readgate_kernel<<<Bn, THREADS>>>(query, memory, emb, qW, qb, oW, ob, out);
}

// round 6
// speedup vs baseline: 1.3841x; 1.0543x over previous
#include <cuda_runtime.h>

// ReadGate, split-2 over M to kill the wave-quantization tail:
//  k1 grid (B, 2): stream memory[b, half], no-max softmax partials -> scratch.
//     First tile loads issued BEFORE the q prologue (loads don't depend on q).
//  k2: combine halves, normalize, out = pooled @ oW.T + ob (coalesced staged oW).

constexpr int Bn = 2048;
constexpr int Mn = 2048;
constexpr int Dn = 64;
constexpr int Vn = 64;
constexpr int THREADS = 256;
constexpr int NHW = 16;                        // half-warps per CTA
constexpr int UNROLL = 4;                      // m-rows per half-warp per iter
constexpr int SPLIT = 2;
constexpr int MCHUNK = Mn / SPLIT;             // 1024
constexpr int ITERS = MCHUNK / (NHW * UNROLL); // 16

__device__ float g_pooled[Bn * SPLIT * Dn];    // unnormalized partial pooled
__device__ float g_sum[Bn * SPLIT];            // partial exp-sums

__global__ __launch_bounds__(THREADS, 4)
void stream_kernel(const int* __restrict__ query,
                   const float* __restrict__ memory,
                   const float* __restrict__ emb,
                   const float* __restrict__ qW,
                   const float* __restrict__ qb)
{
    __shared__ float w_sh[Dn * 65];
    __shared__ float e_sh[Dn];
    __shared__ float q_sh[Dn];
    __shared__ float pooled_sh[NHW][Dn];
    __shared__ float sum_sh[NHW];

    const int b   = blockIdx.x;
    const int s   = blockIdx.y;
    const int tid = threadIdx.x;
    const int hw   = tid >> 4;
    const int lane = tid & 15;

    const float4* __restrict__ mrow =
        reinterpret_cast<const float4*>(memory + (size_t)b * (Mn * Dn)
                                               + (size_t)s * (MCHUNK * Dn)) + lane;

    // ---- issue first tile loads IMMEDIATELY (independent of q) ----
    float4 v[UNROLL];
    #pragma unroll
    for (int j = 0; j < UNROLL; ++j)
        v[j] = __ldcs(mrow + (size_t)(hw + j * NHW) * (Dn / 4));

    // ---- prologue overlapped with loads in flight: stage qW, compute q ----
    #pragma unroll
    for (int i = tid; i < Dn * Dn; i += THREADS)
        w_sh[(i >> 6) * 65 + (i & 63)] = qW[i];
    if (tid < Dn)
        e_sh[tid] = emb[query[b] * Dn + tid];
    __syncthreads();

    if (tid < Dn) {
        float acc = qb[tid];
        #pragma unroll
        for (int k = 0; k < Dn; ++k)
            acc = fmaf(e_sh[k], w_sh[tid * 65 + k], acc);
        q_sh[tid] = acc;
    }
    __syncthreads();

    const float q0 = q_sh[lane * 4 + 0];
    const float q1 = q_sh[lane * 4 + 1];
    const float q2 = q_sh[lane * 4 + 2];
    const float q3 = q_sh[lane * 4 + 3];

    float rsum = 0.f;
    float a0 = 0.f, a1 = 0.f, a2 = 0.f, a3 = 0.f;

    #pragma unroll 1
    for (int it = 0; it < ITERS; ++it) {
        // prefetch next iteration, clamped (last iter re-fetches L2-hot tile)
        const int nit = (it + 1 < ITERS) ? (it + 1) : (ITERS - 1);
        float4 nv[UNROLL];
        #pragma unroll
        for (int j = 0; j < UNROLL; ++j)
            nv[j] = __ldcs(mrow + (size_t)(hw + nit * (NHW * UNROLL) + j * NHW) * (Dn / 4));

        #pragma unroll
        for (int j = 0; j < UNROLL; ++j) {
            float sv = fmaf(v[j].x, q0, fmaf(v[j].y, q1, fmaf(v[j].z, q2, v[j].w * q3)));
            sv += __shfl_xor_sync(0xffffffffu, sv, 8);
            sv += __shfl_xor_sync(0xffffffffu, sv, 4);
            sv += __shfl_xor_sync(0xffffffffu, sv, 2);
            sv += __shfl_xor_sync(0xffffffffu, sv, 1);
            const float p = __expf(sv * 0.125f);   // no max-subtraction: |s/8| <~ 5
            rsum += p;
            a0 = fmaf(p, v[j].x, a0);
            a1 = fmaf(p, v[j].y, a1);
            a2 = fmaf(p, v[j].z, a2);
            a3 = fmaf(p, v[j].w, a3);
        }

        #pragma unroll
        for (int j = 0; j < UNROLL; ++j) v[j] = nv[j];
    }

    pooled_sh[hw][lane * 4 + 0] = a0;
    pooled_sh[hw][lane * 4 + 1] = a1;
    pooled_sh[hw][lane * 4 + 2] = a2;
    pooled_sh[hw][lane * 4 + 3] = a3;
    if (lane == 0) sum_sh[hw] = rsum;
    __syncthreads();

    if (tid < Dn) {
        float pl = 0.f;
        #pragma unroll
        for (int p = 0; p < NHW; ++p) pl += pooled_sh[p][tid];
        g_pooled[((size_t)b * SPLIT + s) * Dn + tid] = pl;
    }
    if (tid == 0) {
        float gs = 0.f;
        #pragma unroll
        for (int p = 0; p < NHW; ++p) gs += sum_sh[p];
        g_sum[b * SPLIT + s] = gs;
    }
}

// ---------------- combine + output projection ----------------
constexpr int ROWS_PER_BLK = 4;   // 512 blocks

__global__ __launch_bounds__(THREADS)
void combine_kernel(const float* __restrict__ oW,
                    const float* __restrict__ ob,
                    float* __restrict__ out)
{
    __shared__ float w_sh[Dn * 65];
    __shared__ float p_sh[ROWS_PER_BLK][Dn];

    const int tid = threadIdx.x;
    const int r   = tid >> 6;       // row group 0..3
    const int vv  = tid & 63;       // output index
    const int b   = blockIdx.x * ROWS_PER_BLK + r;

    // stage oW coalesced, padded
    #pragma unroll
    for (int i = tid; i < Dn * Dn; i += THREADS)
        w_sh[(i >> 6) * 65 + (i & 63)] = oW[i];

    // normalized pooled for this row
    float pl = g_pooled[((size_t)b * SPLIT + 0) * Dn + vv]
             + g_pooled[((size_t)b * SPLIT + 1) * Dn + vv];
    float gs = g_sum[b * SPLIT + 0] + g_sum[b * SPLIT + 1];
    p_sh[r][vv] = pl / gs;
    __syncthreads();

    float acc = ob[vv];
    #pragma unroll
    for (int d = 0; d < Dn; ++d)
        acc = fmaf(p_sh[r][d], w_sh[vv * 65 + d], acc);
    out[(size_t)b * Vn + vv] = acc;
}

extern "C" void kernel_launch(void* const* d_in, const int* in_sizes, int n_in,
                              void* d_out, int out_size)
{
    const int*   query  = (const int*)  d_in[0];
    const float* memory = (const float*)d_in[1];
    const float* emb    = (const float*)d_in[2];
    const float* qW     = (const float*)d_in[3];
    const float* qb     = (const float*)d_in[4];
    const float* oW     = (const float*)d_in[5];
    const float* ob     = (const float*)d_in[6];
    float* out = (float*)d_out;

    stream_kernel<<<dim3(Bn, SPLIT), THREADS>>>(query, memory, emb, qW, qb);
    combine_kernel<<<Bn / ROWS_PER_BLK, THREADS>>>(oW, ob, out);
}